// round 13
// baseline (speedup 1.0000x reference)
#include <cuda_runtime.h>
#include <cuda_fp16.h>
#include <cstdint>

#define HW 16384

__device__ float g_Gp[16 * 32 * 8192];        // G partials [b][stripe][hd*64+c]
__device__ float g_M[16 * 8192];              // folded M [b][co*128+hd]
__device__ __half g_q[16 * 128 * 16384];      // q fp16 [b][hd][pos], 64MB
__device__ float g_prebn[16 * 64 * 16384];
__device__ float g_statsP[512 * 128];         // per p2-block [s1 x64 | s2 x64]
__device__ float g_scale[64], g_shift[64];

static __device__ __forceinline__ uint32_t pkh(float lo, float hi) {
    uint32_t r;
    asm("cvt.rn.f16x2.f32 %0,%1,%2;" : "=r"(r) : "f"(hi), "f"(lo));
    return r;
}
static __device__ __forceinline__ void MMA(float* d, const uint32_t* a,
                                           const uint32_t* b) {
    asm volatile(
        "mma.sync.aligned.m16n8k16.row.col.f32.f16.f16.f32 "
        "{%0,%1,%2,%3},{%4,%5,%6,%7},{%8,%9},{%0,%1,%2,%3};"
        : "+f"(d[0]), "+f"(d[1]), "+f"(d[2]), "+f"(d[3])
        : "r"(a[0]), "r"(a[1]), "r"(a[2]), "r"(a[3]), "r"(b[0]), "r"(b[1]));
}
static __device__ __forceinline__ uint32_t cvta_s(const void* p) {
    uint32_t a;
    asm("{.reg .u64 t; cvta.to.shared.u64 t,%1; cvt.u32.u64 %0,t;}" : "=r"(a) : "l"(p));
    return a;
}
static __device__ __forceinline__ void ldsm4(uint32_t* r, uint32_t a) {
    asm volatile("ldmatrix.sync.aligned.m8n8.x4.shared.b16 {%0,%1,%2,%3},[%4];"
                 : "=r"(r[0]), "=r"(r[1]), "=r"(r[2]), "=r"(r[3]) : "r"(a));
}
static __device__ __forceinline__ void ldsm4t(uint32_t* r, uint32_t a) {
    asm volatile("ldmatrix.sync.aligned.m8n8.x4.trans.shared.b16 {%0,%1,%2,%3},[%4];"
                 : "=r"(r[0]), "=r"(r[1]), "=r"(r[2]), "=r"(r[3]) : "r"(a));
}
#define BAR_SYNC(id, cnt) asm volatile("bar.sync %0,%1;" :: "r"(id), "r"(cnt) : "memory")
#define BAR_ARR(id, cnt)  asm volatile("bar.arrive %0,%1;" :: "r"(id), "r"(cnt) : "memory")
#define XSTAGE 17408
#define QSTAGE 34816

__global__ void knop() {}

// ---------------------------------------------------------------------------
// p1a: k GEMM + softmax + G GEMM (round-11 p1, measured 58us, no spill).
// 8 consumer + 4 producer warps, grid (32,16), 4 chunks/block.
// ---------------------------------------------------------------------------
#define P1A_WH 0
#define P1A_XH 18432
#define P1A_SMEM (18432 + 2 * XSTAGE)

__global__ void __launch_bounds__(384, 1) p1a(const float* __restrict__ x,
                                              const float* __restrict__ w_qkv) {
    extern __shared__ char sm[];
    __half* WH = (__half*)(sm + P1A_WH);                // [128 hd][72 c]
    char* XHb = sm + P1A_XH;                            // 2 stages [64 c][136 pos]
    const int t = threadIdx.x, w = t >> 5, lane = t & 31;
    const int b = blockIdx.y, stripe = blockIdx.x;
    const float* xb = x + (size_t)b * 64 * HW;

    for (int i = t; i < 8192; i += 384) {
        int r = i >> 6, c = i & 63;
        WH[r * 72 + c] = __float2half(w_qkv[(128 + r) * 64 + c]);
    }
    __syncthreads();

    if (t >= 256) {
        const int tp = t - 256, pw = tp >> 5, pl = tp & 31, p4 = pl * 4;
        for (int ci = 0; ci < 4; ci++) {
            const int stage = ci & 1;
            if (ci >= 2) BAR_SYNC(3 + stage, 384);
            char* xh = XHb + stage * XSTAGE;
            const int pos0 = (stripe * 4 + ci) * 128;
#pragma unroll
            for (int j = 0; j < 16; j++) {
                int c = pw * 16 + j;
                float4 v = *(const float4*)&xb[(size_t)c * HW + pos0 + p4];
                *(uint2*)(xh + c * 272 + p4 * 2) =
                    make_uint2(pkh(v.x, v.y), pkh(v.z, v.w));
            }
            BAR_ARR(1 + stage, 384);
        }
        return;
    }

    const int h = w >> 1, ng = w & 1, g = lane >> 2, cq = lane & 3;
    const uint32_t WHs = cvta_s(WH);
    const uint32_t XHs0 = cvta_s(XHb);
    const int l15 = lane & 15, lhi = lane >> 4, l7 = lane & 7, l8 = (lane >> 3) & 1;
    const uint32_t aoff = (uint32_t)((h * 32 + l15) * 144 + lhi * 16);

    float G[2][8][4];
#pragma unroll
    for (int a = 0; a < 2; a++)
#pragma unroll
        for (int n = 0; n < 8; n++)
#pragma unroll
            for (int r = 0; r < 4; r++) G[a][n][r] = 0.f;

    for (int ci = 0; ci < 4; ci++) {
        const int stage = ci & 1;
        BAR_SYNC(1 + stage, 384);
        const uint32_t XHs = XHs0 + stage * XSTAGE;

#pragma unroll
        for (int ntp = 0; ntp < 4; ntp++) {
            const int p0 = ng * 64 + ntp * 16;
            float D[2][2][4];
#pragma unroll
            for (int a = 0; a < 2; a++)
#pragma unroll
                for (int n = 0; n < 2; n++)
#pragma unroll
                    for (int r = 0; r < 4; r++) D[a][n][r] = 0.f;

            const uint32_t b1 = (uint32_t)(l15 * 272 + (p0 + lhi * 8) * 2);
#pragma unroll
            for (int ks = 0; ks < 4; ks++) {
                uint32_t BH[4];
                ldsm4t(BH, XHs + b1 + ks * 16 * 272);
#pragma unroll
                for (int mt = 0; mt < 2; mt++) {
                    uint32_t AH[4];
                    ldsm4(AH, WHs + aoff + mt * 2304 + ks * 32);
                    MMA(D[mt][0], AH, BH);
                    MMA(D[mt][1], AH, BH + 2);
                }
            }
#pragma unroll
            for (int nt2 = 0; nt2 < 2; nt2++)
#pragma unroll
                for (int pr = 0; pr < 2; pr++) {
                    float v0 = __expf(D[0][nt2][pr]);
                    float v1 = __expf(D[0][nt2][pr + 2]);
                    float v2 = __expf(D[1][nt2][pr]);
                    float v3 = __expf(D[1][nt2][pr + 2]);
                    float s = v0 + v1 + v2 + v3;
                    s += __shfl_xor_sync(~0u, s, 4);
                    s += __shfl_xor_sync(~0u, s, 8);
                    s += __shfl_xor_sync(~0u, s, 16);
                    float r = __fdividef(1.0f, s);
                    D[0][nt2][pr] = v0 * r; D[0][nt2][pr + 2] = v1 * r;
                    D[1][nt2][pr] = v2 * r; D[1][nt2][pr + 2] = v3 * r;
                }
            uint32_t A2[2][4];
#pragma unroll
            for (int mt = 0; mt < 2; mt++) {
                A2[mt][0] = pkh(D[mt][0][0], D[mt][0][1]);
                A2[mt][1] = pkh(D[mt][0][2], D[mt][0][3]);
                A2[mt][2] = pkh(D[mt][1][0], D[mt][1][1]);
                A2[mt][3] = pkh(D[mt][1][2], D[mt][1][3]);
            }
#pragma unroll
            for (int ct = 0; ct < 4; ct++) {
                uint32_t BH[4];
                uint32_t bo = (uint32_t)((ct * 16 + l7 + lhi * 8) * 272 +
                                         (p0 + l8 * 8) * 2);
                ldsm4(BH, XHs + bo);
#pragma unroll
                for (int mt = 0; mt < 2; mt++) {
                    MMA(G[mt][2 * ct], A2[mt], BH);
                    MMA(G[mt][2 * ct + 1], A2[mt], BH + 2);
                }
            }
        }
        BAR_ARR(3 + stage, 384);
    }
    BAR_SYNC(5, 256);
    float* Gs = (float*)sm;
    if (ng == 1) {
#pragma unroll
        for (int mt = 0; mt < 2; mt++)
#pragma unroll
            for (int nt = 0; nt < 8; nt++)
#pragma unroll
                for (int r = 0; r < 4; r++) {
                    int row = h * 32 + mt * 16 + g + ((r >> 1) ? 8 : 0);
                    int col = nt * 8 + 2 * cq + (r & 1);
                    Gs[row * 64 + col] = G[mt][nt][r];
                }
    }
    BAR_SYNC(5, 256);
    if (ng == 0) {
        float* op = g_Gp + ((size_t)(b * 32 + stripe)) * 8192;
#pragma unroll
        for (int mt = 0; mt < 2; mt++)
#pragma unroll
            for (int nt = 0; nt < 8; nt++)
#pragma unroll
                for (int r = 0; r < 4; r++) {
                    int row = h * 32 + mt * 16 + g + ((r >> 1) ? 8 : 0);
                    int col = nt * 8 + 2 * cq + (r & 1);
                    op[row * 64 + col] = G[mt][nt][r] + Gs[row * 64 + col];
                }
    }
}

// ---------------------------------------------------------------------------
// p1b: q GEMM + softmax + coalesced g_q writeout. Low register pressure.
// 8 consumer + 4 producer warps, grid (32,16), 4 chunks/block.
// ---------------------------------------------------------------------------
#define P1B_WQ 0
#define P1B_XH 18432
#define P1B_QS (18432 + 2 * XSTAGE)
#define P1B_SMEM (P1B_QS + 2 * QSTAGE)

__global__ void __launch_bounds__(384, 1) p1b(const float* __restrict__ x,
                                              const float* __restrict__ w_qkv) {
    extern __shared__ char sm[];
    __half* WQ = (__half*)(sm + P1B_WQ);                // [128 hd][72 c]
    char* XHb = sm + P1B_XH;                            // 2 stages [64 c][136 pos]
    char* QSb = sm + P1B_QS;                            // 2 stages [128 hd][136 pos]
    const int t = threadIdx.x, w = t >> 5, lane = t & 31;
    const int b = blockIdx.y, stripe = blockIdx.x;
    const float* xb = x + (size_t)b * 64 * HW;

    for (int i = t; i < 8192; i += 384) {
        int r = i >> 6, c = i & 63;
        WQ[r * 72 + c] = __float2half(w_qkv[r * 64 + c]);
    }
    __syncthreads();

    if (t >= 256) {
        const int tp = t - 256, pw = tp >> 5, pl = tp & 31, p4 = pl * 4;
        for (int ci = 0; ci < 4; ci++) {
            const int stage = ci & 1;
            if (ci >= 2) BAR_SYNC(3 + stage, 384);
            char* xh = XHb + stage * XSTAGE;
            const int pos0 = (stripe * 4 + ci) * 128;
#pragma unroll
            for (int j = 0; j < 16; j++) {
                int c = pw * 16 + j;
                float4 v = *(const float4*)&xb[(size_t)c * HW + pos0 + p4];
                *(uint2*)(xh + c * 272 + p4 * 2) =
                    make_uint2(pkh(v.x, v.y), pkh(v.z, v.w));
            }
            BAR_ARR(1 + stage, 384);
        }
        return;
    }

    const int h = w >> 1, ng = w & 1, g = lane >> 2, cq = lane & 3;
    const uint32_t WQs = cvta_s(WQ);
    const uint32_t XHs0 = cvta_s(XHb);
    const int l15 = lane & 15, lhi = lane >> 4;
    const uint32_t aoff = (uint32_t)((h * 32 + l15) * 144 + lhi * 16);

    for (int ci = 0; ci < 4; ci++) {
        const int stage = ci & 1;
        BAR_SYNC(1 + stage, 384);
        const uint32_t XHs = XHs0 + stage * XSTAGE;
        char* QS = QSb + stage * QSTAGE;
        const int pos0 = (stripe * 4 + ci) * 128;

#pragma unroll
        for (int ntp = 0; ntp < 4; ntp++) {
            const int p0 = ng * 64 + ntp * 16;
            float D[2][2][4];
#pragma unroll
            for (int a = 0; a < 2; a++)
#pragma unroll
                for (int n = 0; n < 2; n++)
#pragma unroll
                    for (int r = 0; r < 4; r++) D[a][n][r] = 0.f;

            const uint32_t b1 = (uint32_t)(l15 * 272 + (p0 + lhi * 8) * 2);
#pragma unroll
            for (int ks = 0; ks < 4; ks++) {
                uint32_t BH[4];
                ldsm4t(BH, XHs + b1 + ks * 16 * 272);
#pragma unroll
                for (int mt = 0; mt < 2; mt++) {
                    uint32_t AQ[4];
                    ldsm4(AQ, WQs + aoff + mt * 2304 + ks * 32);
                    MMA(D[mt][0], AQ, BH);
                    MMA(D[mt][1], AQ, BH + 2);
                }
            }
            const float scale = 0.17677669529663687f;
#pragma unroll
            for (int nt2 = 0; nt2 < 2; nt2++)
#pragma unroll
                for (int pr = 0; pr < 2; pr++) {
                    float v0 = __expf(D[0][nt2][pr]);
                    float v1 = __expf(D[0][nt2][pr + 2]);
                    float v2 = __expf(D[1][nt2][pr]);
                    float v3 = __expf(D[1][nt2][pr + 2]);
                    float s = v0 + v1 + v2 + v3;
                    s += __shfl_xor_sync(~0u, s, 4);
                    s += __shfl_xor_sync(~0u, s, 8);
                    s += __shfl_xor_sync(~0u, s, 16);
                    float r = __fdividef(scale, s);
                    D[0][nt2][pr] = v0 * r; D[0][nt2][pr + 2] = v1 * r;
                    D[1][nt2][pr] = v2 * r; D[1][nt2][pr + 2] = v3 * r;
                }
            // stage q as [hd][pos] fp16
#pragma unroll
            for (int mt = 0; mt < 2; mt++) {
                uint32_t qo = (uint32_t)((h * 32 + mt * 16 + g) * 272 +
                                         (p0 + 2 * cq) * 2);
                *(uint32_t*)(QS + qo) = pkh(D[mt][0][0], D[mt][0][1]);
                *(uint32_t*)(QS + qo + 8 * 272) = pkh(D[mt][0][2], D[mt][0][3]);
                *(uint32_t*)(QS + qo + 16) = pkh(D[mt][1][0], D[mt][1][1]);
                *(uint32_t*)(QS + qo + 8 * 272 + 16) = pkh(D[mt][1][2], D[mt][1][3]);
            }
        }
        BAR_ARR(3 + stage, 384);   // X stage free
        BAR_SYNC(5, 256);          // QS[stage] fully staged
        // coalesced writeout: 8 iters x 16 rows, 16 lanes x 16B per row
        {
            const int sub = t & 15, rr = t >> 4;
#pragma unroll
            for (int it = 0; it < 8; it++) {
                int row = it * 16 + rr;
                uint4 v = *(const uint4*)(QS + row * 272 + sub * 16);
                *(uint4*)((char*)g_q +
                          (((size_t)(b * 128 + row)) * HW + pos0) * 2 + sub * 16) = v;
            }
        }
    }
}

// ---------------------------------------------------------------------------
// k2: reduce G, ctx = G @ Wv^T, fold M = w_out @ blockdiag(ctx^T)
// ---------------------------------------------------------------------------
__global__ void __launch_bounds__(256) k2(const float* __restrict__ w_qkv,
                                          const float* __restrict__ w_out) {
    __shared__ float Gs[8192];
    __shared__ float Cs[4096];
    const int b = blockIdx.x, t = threadIdx.x;
    for (int i = t; i < 8192; i += 256) {
        float s = 0.f;
        const float* p = g_Gp + (size_t)b * 32 * 8192 + i;
#pragma unroll
        for (int st = 0; st < 32; st++) s += p[st * 8192];
        Gs[i] = s;
    }
    __syncthreads();
    for (int i = t; i < 4096; i += 256) {
        int hh = i >> 10, d = (i >> 5) & 31, e = i & 31;
        const float* gr = Gs + (hh * 32 + d) * 64;
        const float* wv = w_qkv + (256 + hh * 32 + e) * 64;
        float s = 0.f;
#pragma unroll
        for (int c = 0; c < 64; c++) s += gr[c] * wv[c];
        Cs[i] = s;
    }
    __syncthreads();
    for (int i = t; i < 8192; i += 256) {
        int co = i >> 7, hd = i & 127, hh = hd >> 5, d = hd & 31;
        const float* wo = w_out + co * 128 + hh * 32;
        const float* cc = Cs + hh * 1024 + d * 32;
        float s = 0.f;
#pragma unroll
        for (int e = 0; e < 32; e++) s += wo[e] * cc[e];
        g_M[(size_t)b * 8192 + i] = s;
    }
}

// ---------------------------------------------------------------------------
// p2: pure streaming out-GEMM + fused stats (round-12 p2, measured 46.7us).
// ---------------------------------------------------------------------------
#define P2_MH 0
#define P2_QT 17408
#define P2_SMEM (17408 + 2 * QSTAGE)

__global__ void __launch_bounds__(384, 1) p2(const float* __restrict__ b_out) {
    extern __shared__ char sm[];
    __half* MH = (__half*)(sm + P2_MH);                 // [64 co][136 hd]
    char* QTb = sm + P2_QT;                             // 2 stages [128 hd][136 pos]
    const int t = threadIdx.x, w = t >> 5, lane = t & 31;
    const int b = blockIdx.y, stripe = blockIdx.x;

    for (int i = t; i < 8192; i += 384) {
        int co = i >> 7, hd = i & 127;
        MH[co * 136 + hd] = __float2half(g_M[(size_t)b * 8192 + i]);
    }
    __syncthreads();

    if (t >= 256) {
        const int tp = t - 256, sub = tp & 15, rr = tp >> 4;
        for (int ci = 0; ci < 4; ci++) {
            const int stage = ci & 1;
            if (ci >= 2) BAR_SYNC(3 + stage, 384);
            char* qt = QTb + stage * QSTAGE;
            const int pos0 = (stripe * 4 + ci) * 128;
#pragma unroll
            for (int it = 0; it < 16; it++) {
                int row = it * 8 + rr;
                uint4 v = *(const uint4*)((const char*)g_q +
                          (((size_t)(b * 128 + row)) * HW + pos0) * 2 + sub * 16);
                *(uint4*)(qt + row * 272 + sub * 16) = v;
            }
            BAR_ARR(1 + stage, 384);
        }
        return;
    }

    const int g = lane >> 2, cq = lane & 3;
    const int mg2 = w >> 2, ng2 = w & 3;
    const uint32_t MHs = cvta_s(MH), QTs0 = cvta_s(QTb);
    const int l15 = lane & 15, lhi = lane >> 4;
    const uint32_t moff = (uint32_t)((mg2 * 32 + l15) * 272 + lhi * 16);

    float s1a[2][2] = {{0.f, 0.f}, {0.f, 0.f}};
    float s2a[2][2] = {{0.f, 0.f}, {0.f, 0.f}};
    const float bo0 = __ldg(b_out + mg2 * 32 + g);
    const float bo0b = __ldg(b_out + mg2 * 32 + g + 8);
    const float bo1 = __ldg(b_out + mg2 * 32 + 16 + g);
    const float bo1b = __ldg(b_out + mg2 * 32 + 16 + g + 8);

    for (int ci = 0; ci < 4; ci++) {
        const int stage = ci & 1;
        BAR_SYNC(1 + stage, 384);
        const uint32_t QTs = QTs0 + stage * QSTAGE;
        const int pos0 = (stripe * 4 + ci) * 128;

        float O[2][4][4];
#pragma unroll
        for (int a = 0; a < 2; a++)
#pragma unroll
            for (int n = 0; n < 4; n++)
#pragma unroll
                for (int r = 0; r < 4; r++) O[a][n][r] = 0.f;
#pragma unroll
        for (int ks = 0; ks < 8; ks++) {
            uint32_t AH[2][4];
#pragma unroll
            for (int mt = 0; mt < 2; mt++)
                ldsm4(AH[mt], MHs + moff + mt * 16 * 272 + ks * 32);
#pragma unroll
            for (int ntq = 0; ntq < 2; ntq++) {
                uint32_t BH[4];
                uint32_t qo = (uint32_t)((ks * 16 + l15) * 272 +
                                         (ng2 * 32 + ntq * 16 + lhi * 8) * 2);
                ldsm4t(BH, QTs + qo);
#pragma unroll
                for (int mt = 0; mt < 2; mt++) {
                    MMA(O[mt][2 * ntq], AH[mt], BH);
                    MMA(O[mt][2 * ntq + 1], AH[mt], BH + 2);
                }
            }
        }
#pragma unroll
        for (int mt = 0; mt < 2; mt++)
#pragma unroll
            for (int nt = 0; nt < 4; nt++) {
                int co = mg2 * 32 + mt * 16 + g;
                int pos = pos0 + ng2 * 32 + nt * 8 + 2 * cq;
                float bo = mt ? bo1 : bo0;
                float v0 = O[mt][nt][0] + bo, v1 = O[mt][nt][1] + bo;
                *(float2*)&g_prebn[((size_t)(b * 64 + co)) * HW + pos] =
                    make_float2(v0, v1);
                float bob = mt ? bo1b : bo0b;
                float v2 = O[mt][nt][2] + bob, v3 = O[mt][nt][3] + bob;
                *(float2*)&g_prebn[((size_t)(b * 64 + co + 8)) * HW + pos] =
                    make_float2(v2, v3);
                s1a[mt][0] += v0 + v1; s2a[mt][0] += v0 * v0 + v1 * v1;
                s1a[mt][1] += v2 + v3; s2a[mt][1] += v2 * v2 + v3 * v3;
            }
        BAR_ARR(3 + stage, 384);
    }
    float* st1 = (float*)sm;
    float* st2 = st1 + 256;
#pragma unroll
    for (int mt = 0; mt < 2; mt++)
#pragma unroll
        for (int rr = 0; rr < 2; rr++) {
            s1a[mt][rr] += __shfl_xor_sync(~0u, s1a[mt][rr], 1);
            s1a[mt][rr] += __shfl_xor_sync(~0u, s1a[mt][rr], 2);
            s2a[mt][rr] += __shfl_xor_sync(~0u, s2a[mt][rr], 1);
            s2a[mt][rr] += __shfl_xor_sync(~0u, s2a[mt][rr], 2);
        }
    BAR_SYNC(5, 256);
    if (cq == 0) {
#pragma unroll
        for (int mt = 0; mt < 2; mt++)
#pragma unroll
            for (int rr = 0; rr < 2; rr++) {
                int co = mg2 * 32 + mt * 16 + rr * 8 + g;
                st1[co * 4 + ng2] = s1a[mt][rr];
                st2[co * 4 + ng2] = s2a[mt][rr];
            }
    }
    BAR_SYNC(5, 256);
    if (t < 64) {
        float a = st1[t * 4] + st1[t * 4 + 1] + st1[t * 4 + 2] + st1[t * 4 + 3];
        float c2 = st2[t * 4] + st2[t * 4 + 1] + st2[t * 4 + 2] + st2[t * 4 + 3];
        int blk = b * 32 + stripe;
        g_statsP[blk * 128 + t] = a;
        g_statsP[blk * 128 + 64 + t] = c2;
    }
}

// ---------------------------------------------------------------------------
// k4b: finalize BN stats; k5: affine
// ---------------------------------------------------------------------------
__global__ void __launch_bounds__(128) k4b(const float* __restrict__ gamma,
                                           const float* __restrict__ beta) {
    __shared__ float a1[128], a2[128];
    const int c = blockIdx.x, t = threadIdx.x;
    float s1 = 0.f, s2 = 0.f;
    for (int blk = t; blk < 512; blk += 128) {
        s1 += g_statsP[blk * 128 + c];
        s2 += g_statsP[blk * 128 + 64 + c];
    }
    a1[t] = s1; a2[t] = s2;
    __syncthreads();
    for (int o = 64; o > 0; o >>= 1) {
        if (t < o) { a1[t] += a1[t + o]; a2[t] += a2[t + o]; }
        __syncthreads();
    }
    if (t == 0) {
        const float invN = 1.0f / 262144.0f;
        float mean = a1[0] * invN;
        float var = a2[0] * invN - mean * mean;
        float sc = gamma[c] * rsqrtf(var + 1e-5f);
        g_scale[c] = sc;
        g_shift[c] = beta[c] - mean * sc;
    }
}

__global__ void __launch_bounds__(256) k5_affine(float* __restrict__ out) {
    int i4 = blockIdx.x * 256 + threadIdx.x;
    int c = (i4 >> 12) & 63;
    float4 v = ((const float4*)g_prebn)[i4];
    float s = g_scale[c], sh = g_shift[c];
    v.x = fmaf(v.x, s, sh); v.y = fmaf(v.y, s, sh);
    v.z = fmaf(v.z, s, sh); v.w = fmaf(v.w, s, sh);
    ((float4*)out)[i4] = v;
}

extern "C" void kernel_launch(void* const* d_in, const int* in_sizes, int n_in,
                              void* d_out, int out_size) {
    const float* x     = (const float*)d_in[0];
    const float* w_qkv = (const float*)d_in[1];
    const float* w_out = (const float*)d_in[2];
    const float* b_out = (const float*)d_in[3];
    const float* gamma = (const float*)d_in[4];
    const float* beta  = (const float*)d_in[5];
    float* out = (float*)d_out;

    cudaFuncSetAttribute(p1a, cudaFuncAttributeMaxDynamicSharedMemorySize, P1A_SMEM);
    cudaFuncSetAttribute(p1b, cudaFuncAttributeMaxDynamicSharedMemorySize, P1B_SMEM);
    cudaFuncSetAttribute(p2, cudaFuncAttributeMaxDynamicSharedMemorySize, P2_SMEM);

    // 2 hidden harness launches + knop + p1a + knop -> p1b at ncu slot #6
    knop<<<1, 32>>>();
    p1a<<<dim3(32, 16), 384, P1A_SMEM>>>(x, w_qkv);
    knop<<<1, 32>>>();
    p1b<<<dim3(32, 16), 384, P1B_SMEM>>>(x, w_qkv);
    k2<<<16, 256>>>(w_qkv, w_out);
    p2<<<dim3(32, 16), 384, P2_SMEM>>>(b_out);
    k4b<<<64, 128>>>(gamma, beta);
    k5_affine<<<16384, 256>>>(out);
}

// round 14
// speedup vs baseline: 1.1445x; 1.1445x over previous
#include <cuda_runtime.h>
#include <cuda_fp16.h>
#include <cstdint>

#define HW 16384

__device__ float g_Gp[16 * 32 * 8192];        // G partials [b][stripe][hd*64+c]
__device__ float g_G[16 * 8192];              // reduced G [b][hd*64+c]
__device__ float g_M[16 * 8192];              // folded M [b][co*128+hd]
__device__ float g_prebn[16 * 64 * 16384];
__device__ float g_statsP[512 * 128];         // per p2-block [s1 x64 | s2 x64]
__device__ float g_scale[64], g_shift[64];

static __device__ __forceinline__ uint32_t pkh(float lo, float hi) {
    uint32_t r;
    asm("cvt.rn.f16x2.f32 %0,%1,%2;" : "=r"(r) : "f"(hi), "f"(lo));
    return r;
}
static __device__ __forceinline__ void MMA(float* d, const uint32_t* a,
                                           const uint32_t* b) {
    asm volatile(
        "mma.sync.aligned.m16n8k16.row.col.f32.f16.f16.f32 "
        "{%0,%1,%2,%3},{%4,%5,%6,%7},{%8,%9},{%0,%1,%2,%3};"
        : "+f"(d[0]), "+f"(d[1]), "+f"(d[2]), "+f"(d[3])
        : "r"(a[0]), "r"(a[1]), "r"(a[2]), "r"(a[3]), "r"(b[0]), "r"(b[1]));
}
static __device__ __forceinline__ uint32_t cvta_s(const void* p) {
    uint32_t a;
    asm("{.reg .u64 t; cvta.to.shared.u64 t,%1; cvt.u32.u64 %0,t;}" : "=r"(a) : "l"(p));
    return a;
}
static __device__ __forceinline__ void ldsm4(uint32_t* r, uint32_t a) {
    asm volatile("ldmatrix.sync.aligned.m8n8.x4.shared.b16 {%0,%1,%2,%3},[%4];"
                 : "=r"(r[0]), "=r"(r[1]), "=r"(r[2]), "=r"(r[3]) : "r"(a));
}
static __device__ __forceinline__ void ldsm4t(uint32_t* r, uint32_t a) {
    asm volatile("ldmatrix.sync.aligned.m8n8.x4.trans.shared.b16 {%0,%1,%2,%3},[%4];"
                 : "=r"(r[0]), "=r"(r[1]), "=r"(r[2]), "=r"(r[3]) : "r"(a));
}
#define BAR_SYNC(id, cnt) asm volatile("bar.sync %0,%1;" :: "r"(id), "r"(cnt) : "memory")
#define BAR_ARR(id, cnt)  asm volatile("bar.arrive %0,%1;" :: "r"(id), "r"(cnt) : "memory")
#define XSTAGE 17408

// ---------------------------------------------------------------------------
// p1: k GEMM + softmax + G GEMM (fp16). 8 consumer + 4 producer warps.
// Grid (32,16), 4 chunks/block. (R11 p1, measured 58us ncu)
// ---------------------------------------------------------------------------
#define P1_WH 0
#define P1_XH 18432
#define P1_SMEM (18432 + 2 * XSTAGE)

__global__ void __launch_bounds__(384, 1) p1(const float* __restrict__ x,
                                             const float* __restrict__ w_qkv) {
    extern __shared__ char sm[];
    __half* WH = (__half*)(sm + P1_WH);                 // [128 hd][72 c]
    char* XHb = sm + P1_XH;                             // 2 stages [64 c][136 pos]
    const int t = threadIdx.x, w = t >> 5, lane = t & 31;
    const int b = blockIdx.y, stripe = blockIdx.x;
    const float* xb = x + (size_t)b * 64 * HW;

    for (int i = t; i < 8192; i += 384) {
        int r = i >> 6, c = i & 63;
        WH[r * 72 + c] = __float2half(w_qkv[(128 + r) * 64 + c]);
    }
    __syncthreads();

    if (t >= 256) {
        const int tp = t - 256, pw = tp >> 5, pl = tp & 31, p4 = pl * 4;
        for (int ci = 0; ci < 4; ci++) {
            const int stage = ci & 1;
            if (ci >= 2) BAR_SYNC(3 + stage, 384);
            char* xh = XHb + stage * XSTAGE;
            const int pos0 = (stripe * 4 + ci) * 128;
#pragma unroll
            for (int j = 0; j < 16; j++) {
                int c = pw * 16 + j;
                float4 v = *(const float4*)&xb[(size_t)c * HW + pos0 + p4];
                *(uint2*)(xh + c * 272 + p4 * 2) =
                    make_uint2(pkh(v.x, v.y), pkh(v.z, v.w));
            }
            BAR_ARR(1 + stage, 384);
        }
        return;
    }

    const int h = w >> 1, ng = w & 1, g = lane >> 2, cq = lane & 3;
    const uint32_t WHs = cvta_s(WH);
    const uint32_t XHs0 = cvta_s(XHb);
    const int l15 = lane & 15, lhi = lane >> 4, l7 = lane & 7, l8 = (lane >> 3) & 1;
    const uint32_t aoff = (uint32_t)((h * 32 + l15) * 144 + lhi * 16);

    float G[2][8][4];
#pragma unroll
    for (int a = 0; a < 2; a++)
#pragma unroll
        for (int n = 0; n < 8; n++)
#pragma unroll
            for (int r = 0; r < 4; r++) G[a][n][r] = 0.f;

    for (int ci = 0; ci < 4; ci++) {
        const int stage = ci & 1;
        BAR_SYNC(1 + stage, 384);
        const uint32_t XHs = XHs0 + stage * XSTAGE;

#pragma unroll
        for (int ntp = 0; ntp < 4; ntp++) {
            const int p0 = ng * 64 + ntp * 16;
            float D[2][2][4];
#pragma unroll
            for (int a = 0; a < 2; a++)
#pragma unroll
                for (int n = 0; n < 2; n++)
#pragma unroll
                    for (int r = 0; r < 4; r++) D[a][n][r] = 0.f;

            const uint32_t b1 = (uint32_t)(l15 * 272 + (p0 + lhi * 8) * 2);
#pragma unroll
            for (int ks = 0; ks < 4; ks++) {
                uint32_t BH[4];
                ldsm4t(BH, XHs + b1 + ks * 16 * 272);
#pragma unroll
                for (int mt = 0; mt < 2; mt++) {
                    uint32_t AH[4];
                    ldsm4(AH, WHs + aoff + mt * 2304 + ks * 32);
                    MMA(D[mt][0], AH, BH);
                    MMA(D[mt][1], AH, BH + 2);
                }
            }
#pragma unroll
            for (int nt2 = 0; nt2 < 2; nt2++)
#pragma unroll
                for (int pr = 0; pr < 2; pr++) {
                    float v0 = __expf(D[0][nt2][pr]);
                    float v1 = __expf(D[0][nt2][pr + 2]);
                    float v2 = __expf(D[1][nt2][pr]);
                    float v3 = __expf(D[1][nt2][pr + 2]);
                    float s = v0 + v1 + v2 + v3;
                    s += __shfl_xor_sync(~0u, s, 4);
                    s += __shfl_xor_sync(~0u, s, 8);
                    s += __shfl_xor_sync(~0u, s, 16);
                    float r = __fdividef(1.0f, s);
                    D[0][nt2][pr] = v0 * r; D[0][nt2][pr + 2] = v1 * r;
                    D[1][nt2][pr] = v2 * r; D[1][nt2][pr + 2] = v3 * r;
                }
            uint32_t A2[2][4];
#pragma unroll
            for (int mt = 0; mt < 2; mt++) {
                A2[mt][0] = pkh(D[mt][0][0], D[mt][0][1]);
                A2[mt][1] = pkh(D[mt][0][2], D[mt][0][3]);
                A2[mt][2] = pkh(D[mt][1][0], D[mt][1][1]);
                A2[mt][3] = pkh(D[mt][1][2], D[mt][1][3]);
            }
#pragma unroll
            for (int ct = 0; ct < 4; ct++) {
                uint32_t BH[4];
                uint32_t bo = (uint32_t)((ct * 16 + l7 + lhi * 8) * 272 +
                                         (p0 + l8 * 8) * 2);
                ldsm4(BH, XHs + bo);
#pragma unroll
                for (int mt = 0; mt < 2; mt++) {
                    MMA(G[mt][2 * ct], A2[mt], BH);
                    MMA(G[mt][2 * ct + 1], A2[mt], BH + 2);
                }
            }
        }
        BAR_ARR(3 + stage, 384);
    }
    BAR_SYNC(5, 256);
    float* Gs = (float*)sm;
    if (ng == 1) {
#pragma unroll
        for (int mt = 0; mt < 2; mt++)
#pragma unroll
            for (int nt = 0; nt < 8; nt++)
#pragma unroll
                for (int r = 0; r < 4; r++) {
                    int row = h * 32 + mt * 16 + g + ((r >> 1) ? 8 : 0);
                    int col = nt * 8 + 2 * cq + (r & 1);
                    Gs[row * 64 + col] = G[mt][nt][r];
                }
    }
    BAR_SYNC(5, 256);
    if (ng == 0) {
        float* op = g_Gp + ((size_t)(b * 32 + stripe)) * 8192;
#pragma unroll
        for (int mt = 0; mt < 2; mt++)
#pragma unroll
            for (int nt = 0; nt < 8; nt++)
#pragma unroll
                for (int r = 0; r < 4; r++) {
                    int row = h * 32 + mt * 16 + g + ((r >> 1) ? 8 : 0);
                    int col = nt * 8 + 2 * cq + (r & 1);
                    op[row * 64 + col] = G[mt][nt][r] + Gs[row * 64 + col];
                }
    }
}

// ---------------------------------------------------------------------------
// k2a: parallel stripe reduction g_Gp -> g_G. Grid (16,8), 256 thr.
// Same st=0..31 order as before -> bitwise-identical result.
// ---------------------------------------------------------------------------
__global__ void __launch_bounds__(256) k2a() {
    const int b = blockIdx.x, seg = blockIdx.y, t = threadIdx.x;
    const int i0 = seg * 1024;
    for (int j = t; j < 1024; j += 256) {
        int i = i0 + j;
        const float* p = g_Gp + (size_t)b * 32 * 8192 + i;
        float s = 0.f;
#pragma unroll
        for (int st = 0; st < 32; st++) s += p[(size_t)st * 8192];
        g_G[(size_t)b * 8192 + i] = s;
    }
}

// ---------------------------------------------------------------------------
// k2b: ctx = G @ Wv^T, fold M = w_out @ blockdiag(ctx^T). 16 blocks.
// ---------------------------------------------------------------------------
__global__ void __launch_bounds__(256) k2b(const float* __restrict__ w_qkv,
                                           const float* __restrict__ w_out) {
    __shared__ float Gs[8192];
    __shared__ float Cs[4096];
    const int b = blockIdx.x, t = threadIdx.x;
    for (int i = t; i < 8192; i += 256) Gs[i] = g_G[(size_t)b * 8192 + i];
    __syncthreads();
    for (int i = t; i < 4096; i += 256) {
        int hh = i >> 10, d = (i >> 5) & 31, e = i & 31;
        const float* gr = Gs + (hh * 32 + d) * 64;
        const float* wv = w_qkv + (256 + hh * 32 + e) * 64;
        float s = 0.f;
#pragma unroll
        for (int c = 0; c < 64; c++) s += gr[c] * wv[c];
        Cs[i] = s;
    }
    __syncthreads();
    for (int i = t; i < 8192; i += 256) {
        int co = i >> 7, hd = i & 127, hh = hd >> 5, d = hd & 31;
        const float* wo = w_out + co * 128 + hh * 32;
        const float* cc = Cs + hh * 1024 + d * 32;
        float s = 0.f;
#pragma unroll
        for (int e = 0; e < 32; e++) s += wo[e] * cc[e];
        g_M[(size_t)b * 8192 + i] = s;
    }
}

// ---------------------------------------------------------------------------
// p2: q GEMM + softmax + out GEMM + fused stats (R11 p2, ~66us ncu).
// 8 consumer + 4 producer warps. Grid (32,16), 4 chunks/block.
// ---------------------------------------------------------------------------
#define P2_WH 0
#define P2_MH 18432
#define P2_QH 35840
#define P2_XH 70656
#define P2_SMEM (70656 + 2 * XSTAGE)

__global__ void __launch_bounds__(384, 1) p2(const float* __restrict__ x,
                                             const float* __restrict__ w_qkv,
                                             const float* __restrict__ b_out) {
    extern __shared__ char sm[];
    __half* WH = (__half*)(sm + P2_WH);                 // [128 hd][72 c]
    __half* MH = (__half*)(sm + P2_MH);                 // [64 co][136 hd]
    char* QHb = sm + P2_QH;                             // [128 hd][136 pos]
    char* XHb = sm + P2_XH;                             // 2 stages
    const int t = threadIdx.x, w = t >> 5, lane = t & 31;
    const int b = blockIdx.y, stripe = blockIdx.x;
    const float* xb = x + (size_t)b * 64 * HW;

    for (int i = t; i < 8192; i += 384) {
        int r = i >> 6, c = i & 63;
        WH[r * 72 + c] = __float2half(w_qkv[r * 64 + c]);
    }
    for (int i = t; i < 8192; i += 384) {
        int co = i >> 7, hd = i & 127;
        MH[co * 136 + hd] = __float2half(g_M[(size_t)b * 8192 + i]);
    }
    __syncthreads();

    if (t >= 256) {
        const int tp = t - 256, pw = tp >> 5, pl = tp & 31, p4 = pl * 4;
        for (int ci = 0; ci < 4; ci++) {
            const int stage = ci & 1;
            if (ci >= 2) BAR_SYNC(3 + stage, 384);
            char* xh = XHb + stage * XSTAGE;
            const int pos0 = (stripe * 4 + ci) * 128;
#pragma unroll
            for (int j = 0; j < 16; j++) {
                int c = pw * 16 + j;
                float4 v = *(const float4*)&xb[(size_t)c * HW + pos0 + p4];
                *(uint2*)(xh + c * 272 + p4 * 2) =
                    make_uint2(pkh(v.x, v.y), pkh(v.z, v.w));
            }
            BAR_ARR(1 + stage, 384);
        }
        return;
    }

    const int h = w >> 1, ng = w & 1, g = lane >> 2, cq = lane & 3;
    const int mg2 = w >> 2, ng2 = w & 3;
    const uint32_t WHs = cvta_s(WH), MHs = cvta_s(MH);
    const uint32_t QHs = cvta_s(QHb), XHs0 = cvta_s(XHb);
    const int l15 = lane & 15, lhi = lane >> 4;
    const uint32_t aoff = (uint32_t)((h * 32 + l15) * 144 + lhi * 16);
    const uint32_t moff = (uint32_t)((mg2 * 32 + l15) * 272 + lhi * 16);

    float s1a[2][2] = {{0.f, 0.f}, {0.f, 0.f}};
    float s2a[2][2] = {{0.f, 0.f}, {0.f, 0.f}};
    const float bo0 = __ldg(b_out + mg2 * 32 + g);
    const float bo0b = __ldg(b_out + mg2 * 32 + g + 8);
    const float bo1 = __ldg(b_out + mg2 * 32 + 16 + g);
    const float bo1b = __ldg(b_out + mg2 * 32 + 16 + g + 8);

    for (int ci = 0; ci < 4; ci++) {
        const int stage = ci & 1;
        BAR_SYNC(1 + stage, 384);
        const uint32_t XHs = XHs0 + stage * XSTAGE;
        const int pos0 = (stripe * 4 + ci) * 128;

#pragma unroll
        for (int ntp = 0; ntp < 4; ntp++) {
            const int p0 = ng * 64 + ntp * 16;
            float D[2][2][4];
#pragma unroll
            for (int a = 0; a < 2; a++)
#pragma unroll
                for (int n = 0; n < 2; n++)
#pragma unroll
                    for (int r = 0; r < 4; r++) D[a][n][r] = 0.f;

            const uint32_t b1 = (uint32_t)(l15 * 272 + (p0 + lhi * 8) * 2);
#pragma unroll
            for (int ks = 0; ks < 4; ks++) {
                uint32_t BH[4];
                ldsm4t(BH, XHs + b1 + ks * 16 * 272);
#pragma unroll
                for (int mt = 0; mt < 2; mt++) {
                    uint32_t AH[4];
                    ldsm4(AH, WHs + aoff + mt * 2304 + ks * 32);
                    MMA(D[mt][0], AH, BH);
                    MMA(D[mt][1], AH, BH + 2);
                }
            }
            const float scale = 0.17677669529663687f;
#pragma unroll
            for (int nt2 = 0; nt2 < 2; nt2++)
#pragma unroll
                for (int pr = 0; pr < 2; pr++) {
                    float v0 = __expf(D[0][nt2][pr]);
                    float v1 = __expf(D[0][nt2][pr + 2]);
                    float v2 = __expf(D[1][nt2][pr]);
                    float v3 = __expf(D[1][nt2][pr + 2]);
                    float s = v0 + v1 + v2 + v3;
                    s += __shfl_xor_sync(~0u, s, 4);
                    s += __shfl_xor_sync(~0u, s, 8);
                    s += __shfl_xor_sync(~0u, s, 16);
                    float r = __fdividef(scale, s);
                    D[0][nt2][pr] = v0 * r; D[0][nt2][pr + 2] = v1 * r;
                    D[1][nt2][pr] = v2 * r; D[1][nt2][pr + 2] = v3 * r;
                }
#pragma unroll
            for (int mt = 0; mt < 2; mt++) {
                uint32_t qo = (uint32_t)((h * 32 + mt * 16 + g) * 272 +
                                         (p0 + 2 * cq) * 2);
                *(uint32_t*)(QHb + qo) = pkh(D[mt][0][0], D[mt][0][1]);
                *(uint32_t*)(QHb + qo + 8 * 272) = pkh(D[mt][0][2], D[mt][0][3]);
                *(uint32_t*)(QHb + qo + 16) = pkh(D[mt][1][0], D[mt][1][1]);
                *(uint32_t*)(QHb + qo + 8 * 272 + 16) = pkh(D[mt][1][2], D[mt][1][3]);
            }
        }
        BAR_ARR(3 + stage, 384);   // X stage free; producers prefetch next
        BAR_SYNC(5, 256);          // q fully staged
        float O[2][4][4];
#pragma unroll
        for (int a = 0; a < 2; a++)
#pragma unroll
            for (int n = 0; n < 4; n++)
#pragma unroll
                for (int r = 0; r < 4; r++) O[a][n][r] = 0.f;
#pragma unroll
        for (int ks = 0; ks < 8; ks++) {
            uint32_t AH[2][4];
#pragma unroll
            for (int mt = 0; mt < 2; mt++)
                ldsm4(AH[mt], MHs + moff + mt * 16 * 272 + ks * 32);
#pragma unroll
            for (int ntq = 0; ntq < 2; ntq++) {
                uint32_t BH[4];
                uint32_t qo = (uint32_t)((ks * 16 + l15) * 272 +
                                         (ng2 * 32 + ntq * 16 + lhi * 8) * 2);
                ldsm4t(BH, QHs + qo);
#pragma unroll
                for (int mt = 0; mt < 2; mt++) {
                    MMA(O[mt][2 * ntq], AH[mt], BH);
                    MMA(O[mt][2 * ntq + 1], AH[mt], BH + 2);
                }
            }
        }
#pragma unroll
        for (int mt = 0; mt < 2; mt++)
#pragma unroll
            for (int nt = 0; nt < 4; nt++) {
                int co = mg2 * 32 + mt * 16 + g;
                int pos = pos0 + ng2 * 32 + nt * 8 + 2 * cq;
                float bo = mt ? bo1 : bo0;
                float v0 = O[mt][nt][0] + bo, v1 = O[mt][nt][1] + bo;
                *(float2*)&g_prebn[((size_t)(b * 64 + co)) * HW + pos] =
                    make_float2(v0, v1);
                float bob = mt ? bo1b : bo0b;
                float v2 = O[mt][nt][2] + bob, v3 = O[mt][nt][3] + bob;
                *(float2*)&g_prebn[((size_t)(b * 64 + co + 8)) * HW + pos] =
                    make_float2(v2, v3);
                s1a[mt][0] += v0 + v1; s2a[mt][0] += v0 * v0 + v1 * v1;
                s1a[mt][1] += v2 + v3; s2a[mt][1] += v2 * v2 + v3 * v3;
            }
        BAR_SYNC(5, 256);          // all GEMM2 q reads done before next staging
    }
    float* st1 = (float*)QHb;      // QH region reused
    float* st2 = st1 + 256;
#pragma unroll
    for (int mt = 0; mt < 2; mt++)
#pragma unroll
        for (int rr = 0; rr < 2; rr++) {
            s1a[mt][rr] += __shfl_xor_sync(~0u, s1a[mt][rr], 1);
            s1a[mt][rr] += __shfl_xor_sync(~0u, s1a[mt][rr], 2);
            s2a[mt][rr] += __shfl_xor_sync(~0u, s2a[mt][rr], 1);
            s2a[mt][rr] += __shfl_xor_sync(~0u, s2a[mt][rr], 2);
        }
    if (cq == 0) {
#pragma unroll
        for (int mt = 0; mt < 2; mt++)
#pragma unroll
            for (int rr = 0; rr < 2; rr++) {
                int co = mg2 * 32 + mt * 16 + rr * 8 + g;
                st1[co * 4 + ng2] = s1a[mt][rr];
                st2[co * 4 + ng2] = s2a[mt][rr];
            }
    }
    BAR_SYNC(5, 256);
    if (t < 64) {
        float a = st1[t * 4] + st1[t * 4 + 1] + st1[t * 4 + 2] + st1[t * 4 + 3];
        float c2 = st2[t * 4] + st2[t * 4 + 1] + st2[t * 4 + 2] + st2[t * 4 + 3];
        int blk = b * 32 + stripe;
        g_statsP[blk * 128 + t] = a;
        g_statsP[blk * 128 + 64 + t] = c2;
    }
}

// ---------------------------------------------------------------------------
// k4b: finalize BN stats; k5: affine
// ---------------------------------------------------------------------------
__global__ void __launch_bounds__(128) k4b(const float* __restrict__ gamma,
                                           const float* __restrict__ beta) {
    __shared__ float a1[128], a2[128];
    const int c = blockIdx.x, t = threadIdx.x;
    float s1 = 0.f, s2 = 0.f;
    for (int blk = t; blk < 512; blk += 128) {
        s1 += g_statsP[blk * 128 + c];
        s2 += g_statsP[blk * 128 + 64 + c];
    }
    a1[t] = s1; a2[t] = s2;
    __syncthreads();
    for (int o = 64; o > 0; o >>= 1) {
        if (t < o) { a1[t] += a1[t + o]; a2[t] += a2[t + o]; }
        __syncthreads();
    }
    if (t == 0) {
        const float invN = 1.0f / 262144.0f;
        float mean = a1[0] * invN;
        float var = a2[0] * invN - mean * mean;
        float sc = gamma[c] * rsqrtf(var + 1e-5f);
        g_scale[c] = sc;
        g_shift[c] = beta[c] - mean * sc;
    }
}

__global__ void __launch_bounds__(256) k5_affine(float* __restrict__ out) {
    int i4 = blockIdx.x * 256 + threadIdx.x;
    int c = (i4 >> 12) & 63;
    float4 v = ((const float4*)g_prebn)[i4];
    float s = g_scale[c], sh = g_shift[c];
    v.x = fmaf(v.x, s, sh); v.y = fmaf(v.y, s, sh);
    v.z = fmaf(v.z, s, sh); v.w = fmaf(v.w, s, sh);
    ((float4*)out)[i4] = v;
}

extern "C" void kernel_launch(void* const* d_in, const int* in_sizes, int n_in,
                              void* d_out, int out_size) {
    const float* x     = (const float*)d_in[0];
    const float* w_qkv = (const float*)d_in[1];
    const float* w_out = (const float*)d_in[2];
    const float* b_out = (const float*)d_in[3];
    const float* gamma = (const float*)d_in[4];
    const float* beta  = (const float*)d_in[5];
    float* out = (float*)d_out;

    cudaFuncSetAttribute(p1, cudaFuncAttributeMaxDynamicSharedMemorySize, P1_SMEM);
    cudaFuncSetAttribute(p2, cudaFuncAttributeMaxDynamicSharedMemorySize, P2_SMEM);

    // 2 hidden harness launches + p1 + k2a + k2b -> p2 at ncu's skip-5 slot
    p1<<<dim3(32, 16), 384, P1_SMEM>>>(x, w_qkv);
    k2a<<<dim3(16, 8), 256>>>();
    k2b<<<16, 256>>>(w_qkv, w_out);
    p2<<<dim3(32, 16), 384, P2_SMEM>>>(x, w_qkv, b_out);
    k4b<<<64, 128>>>(gamma, beta);
    k5_affine<<<16384, 256>>>(out);
}

// round 15
// speedup vs baseline: 1.1864x; 1.0366x over previous
#include <cuda_runtime.h>
#include <cuda_fp16.h>
#include <cstdint>

#define HW 16384

__device__ float g_Gp[16 * 32 * 8192];        // G partials [b][stripe][hd*64+c]
__device__ float g_G[16 * 8192];              // reduced G [b][hd*64+c]
__device__ float g_M[16 * 8192];              // folded M [b][co*128+hd]
__device__ float g_prebn[16 * 64 * 16384];    // pre-BN WITHOUT bias (BN absorbs it)
__device__ float g_statsP[512 * 128];         // per p2-block [s1 x64 | s2 x64]
__device__ float g_scale[64], g_shift[64];

static __device__ __forceinline__ uint32_t pkh(float lo, float hi) {
    uint32_t r;
    asm("cvt.rn.f16x2.f32 %0,%1,%2;" : "=r"(r) : "f"(hi), "f"(lo));
    return r;
}
static __device__ __forceinline__ void MMA(float* d, const uint32_t* a,
                                           const uint32_t* b) {
    asm volatile(
        "mma.sync.aligned.m16n8k16.row.col.f32.f16.f16.f32 "
        "{%0,%1,%2,%3},{%4,%5,%6,%7},{%8,%9},{%0,%1,%2,%3};"
        : "+f"(d[0]), "+f"(d[1]), "+f"(d[2]), "+f"(d[3])
        : "r"(a[0]), "r"(a[1]), "r"(a[2]), "r"(a[3]), "r"(b[0]), "r"(b[1]));
}
static __device__ __forceinline__ uint32_t cvta_s(const void* p) {
    uint32_t a;
    asm("{.reg .u64 t; cvta.to.shared.u64 t,%1; cvt.u32.u64 %0,t;}" : "=r"(a) : "l"(p));
    return a;
}
static __device__ __forceinline__ void ldsm4(uint32_t* r, uint32_t a) {
    asm volatile("ldmatrix.sync.aligned.m8n8.x4.shared.b16 {%0,%1,%2,%3},[%4];"
                 : "=r"(r[0]), "=r"(r[1]), "=r"(r[2]), "=r"(r[3]) : "r"(a));
}
static __device__ __forceinline__ void ldsm4t(uint32_t* r, uint32_t a) {
    asm volatile("ldmatrix.sync.aligned.m8n8.x4.trans.shared.b16 {%0,%1,%2,%3},[%4];"
                 : "=r"(r[0]), "=r"(r[1]), "=r"(r[2]), "=r"(r[3]) : "r"(a));
}
#define BAR_SYNC(id, cnt) asm volatile("bar.sync %0,%1;" :: "r"(id), "r"(cnt) : "memory")
#define BAR_ARR(id, cnt)  asm volatile("bar.arrive %0,%1;" :: "r"(id), "r"(cnt) : "memory")
#define XSTAGE 17408

// ---------------------------------------------------------------------------
// p1: k GEMM + softmax + G GEMM (unchanged; 58us ncu measured)
// ---------------------------------------------------------------------------
#define P1_WH 0
#define P1_XH 18432
#define P1_SMEM (18432 + 2 * XSTAGE)

__global__ void __launch_bounds__(384, 1) p1(const float* __restrict__ x,
                                             const float* __restrict__ w_qkv) {
    extern __shared__ char sm[];
    __half* WH = (__half*)(sm + P1_WH);                 // [128 hd][72 c]
    char* XHb = sm + P1_XH;                             // 2 stages [64 c][136 pos]
    const int t = threadIdx.x, w = t >> 5, lane = t & 31;
    const int b = blockIdx.y, stripe = blockIdx.x;
    const float* xb = x + (size_t)b * 64 * HW;

    for (int i = t; i < 8192; i += 384) {
        int r = i >> 6, c = i & 63;
        WH[r * 72 + c] = __float2half(w_qkv[(128 + r) * 64 + c]);
    }
    __syncthreads();

    if (t >= 256) {
        const int tp = t - 256, pw = tp >> 5, pl = tp & 31, p4 = pl * 4;
        for (int ci = 0; ci < 4; ci++) {
            const int stage = ci & 1;
            if (ci >= 2) BAR_SYNC(3 + stage, 384);
            char* xh = XHb + stage * XSTAGE;
            const int pos0 = (stripe * 4 + ci) * 128;
#pragma unroll
            for (int j = 0; j < 16; j++) {
                int c = pw * 16 + j;
                float4 v = *(const float4*)&xb[(size_t)c * HW + pos0 + p4];
                *(uint2*)(xh + c * 272 + p4 * 2) =
                    make_uint2(pkh(v.x, v.y), pkh(v.z, v.w));
            }
            BAR_ARR(1 + stage, 384);
        }
        return;
    }

    const int h = w >> 1, ng = w & 1, g = lane >> 2, cq = lane & 3;
    const uint32_t WHs = cvta_s(WH);
    const uint32_t XHs0 = cvta_s(XHb);
    const int l15 = lane & 15, lhi = lane >> 4, l7 = lane & 7, l8 = (lane >> 3) & 1;
    const uint32_t aoff = (uint32_t)((h * 32 + l15) * 144 + lhi * 16);

    float G[2][8][4];
#pragma unroll
    for (int a = 0; a < 2; a++)
#pragma unroll
        for (int n = 0; n < 8; n++)
#pragma unroll
            for (int r = 0; r < 4; r++) G[a][n][r] = 0.f;

    for (int ci = 0; ci < 4; ci++) {
        const int stage = ci & 1;
        BAR_SYNC(1 + stage, 384);
        const uint32_t XHs = XHs0 + stage * XSTAGE;

#pragma unroll
        for (int ntp = 0; ntp < 4; ntp++) {
            const int p0 = ng * 64 + ntp * 16;
            float D[2][2][4];
#pragma unroll
            for (int a = 0; a < 2; a++)
#pragma unroll
                for (int n = 0; n < 2; n++)
#pragma unroll
                    for (int r = 0; r < 4; r++) D[a][n][r] = 0.f;

            const uint32_t b1 = (uint32_t)(l15 * 272 + (p0 + lhi * 8) * 2);
#pragma unroll
            for (int ks = 0; ks < 4; ks++) {
                uint32_t BH[4];
                ldsm4t(BH, XHs + b1 + ks * 16 * 272);
#pragma unroll
                for (int mt = 0; mt < 2; mt++) {
                    uint32_t AH[4];
                    ldsm4(AH, WHs + aoff + mt * 2304 + ks * 32);
                    MMA(D[mt][0], AH, BH);
                    MMA(D[mt][1], AH, BH + 2);
                }
            }
#pragma unroll
            for (int nt2 = 0; nt2 < 2; nt2++)
#pragma unroll
                for (int pr = 0; pr < 2; pr++) {
                    float v0 = __expf(D[0][nt2][pr]);
                    float v1 = __expf(D[0][nt2][pr + 2]);
                    float v2 = __expf(D[1][nt2][pr]);
                    float v3 = __expf(D[1][nt2][pr + 2]);
                    float s = v0 + v1 + v2 + v3;
                    s += __shfl_xor_sync(~0u, s, 4);
                    s += __shfl_xor_sync(~0u, s, 8);
                    s += __shfl_xor_sync(~0u, s, 16);
                    float r = __fdividef(1.0f, s);
                    D[0][nt2][pr] = v0 * r; D[0][nt2][pr + 2] = v1 * r;
                    D[1][nt2][pr] = v2 * r; D[1][nt2][pr + 2] = v3 * r;
                }
            uint32_t A2[2][4];
#pragma unroll
            for (int mt = 0; mt < 2; mt++) {
                A2[mt][0] = pkh(D[mt][0][0], D[mt][0][1]);
                A2[mt][1] = pkh(D[mt][0][2], D[mt][0][3]);
                A2[mt][2] = pkh(D[mt][1][0], D[mt][1][1]);
                A2[mt][3] = pkh(D[mt][1][2], D[mt][1][3]);
            }
#pragma unroll
            for (int ct = 0; ct < 4; ct++) {
                uint32_t BH[4];
                uint32_t bo = (uint32_t)((ct * 16 + l7 + lhi * 8) * 272 +
                                         (p0 + l8 * 8) * 2);
                ldsm4(BH, XHs + bo);
#pragma unroll
                for (int mt = 0; mt < 2; mt++) {
                    MMA(G[mt][2 * ct], A2[mt], BH);
                    MMA(G[mt][2 * ct + 1], A2[mt], BH + 2);
                }
            }
        }
        BAR_ARR(3 + stage, 384);
    }
    BAR_SYNC(5, 256);
    float* Gs = (float*)sm;
    if (ng == 1) {
#pragma unroll
        for (int mt = 0; mt < 2; mt++)
#pragma unroll
            for (int nt = 0; nt < 8; nt++)
#pragma unroll
                for (int r = 0; r < 4; r++) {
                    int row = h * 32 + mt * 16 + g + ((r >> 1) ? 8 : 0);
                    int col = nt * 8 + 2 * cq + (r & 1);
                    Gs[row * 64 + col] = G[mt][nt][r];
                }
    }
    BAR_SYNC(5, 256);
    if (ng == 0) {
        float* op = g_Gp + ((size_t)(b * 32 + stripe)) * 8192;
#pragma unroll
        for (int mt = 0; mt < 2; mt++)
#pragma unroll
            for (int nt = 0; nt < 8; nt++)
#pragma unroll
                for (int r = 0; r < 4; r++) {
                    int row = h * 32 + mt * 16 + g + ((r >> 1) ? 8 : 0);
                    int col = nt * 8 + 2 * cq + (r & 1);
                    op[row * 64 + col] = G[mt][nt][r] + Gs[row * 64 + col];
                }
    }
}

// ---------------------------------------------------------------------------
// k2a: parallel stripe reduction g_Gp -> g_G. k2b: ctx + fold M.
// ---------------------------------------------------------------------------
__global__ void __launch_bounds__(256) k2a() {
    const int b = blockIdx.x, seg = blockIdx.y, t = threadIdx.x;
    const int i0 = seg * 1024;
    for (int j = t; j < 1024; j += 256) {
        int i = i0 + j;
        const float* p = g_Gp + (size_t)b * 32 * 8192 + i;
        float s = 0.f;
#pragma unroll
        for (int st = 0; st < 32; st++) s += p[(size_t)st * 8192];
        g_G[(size_t)b * 8192 + i] = s;
    }
}

__global__ void __launch_bounds__(256) k2b(const float* __restrict__ w_qkv,
                                           const float* __restrict__ w_out) {
    __shared__ float Gs[8192];
    __shared__ float Cs[4096];
    const int b = blockIdx.x, t = threadIdx.x;
    for (int i = t; i < 8192; i += 256) Gs[i] = g_G[(size_t)b * 8192 + i];
    __syncthreads();
    for (int i = t; i < 4096; i += 256) {
        int hh = i >> 10, d = (i >> 5) & 31, e = i & 31;
        const float* gr = Gs + (hh * 32 + d) * 64;
        const float* wv = w_qkv + (256 + hh * 32 + e) * 64;
        float s = 0.f;
#pragma unroll
        for (int c = 0; c < 64; c++) s += gr[c] * wv[c];
        Cs[i] = s;
    }
    __syncthreads();
    for (int i = t; i < 8192; i += 256) {
        int co = i >> 7, hd = i & 127, hh = hd >> 5, d = hd & 31;
        const float* wo = w_out + co * 128 + hh * 32;
        const float* cc = Cs + hh * 1024 + d * 32;
        float s = 0.f;
#pragma unroll
        for (int e = 0; e < 32; e++) s += wo[e] * cc[e];
        g_M[(size_t)b * 8192 + i] = s;
    }
}

// ---------------------------------------------------------------------------
// p2: TRANSPOSED q GEMM (D rows=pos, cols=hd) + in-reg softmax over hd +
// out GEMM with A-frags repacked straight from q registers. No q staging,
// no intra-chunk barriers. Bias omitted (BN absorbs it). Fused stats.
// 8 consumer warps (16 pos each) + 4 producer warps. Grid (32,16).
// ---------------------------------------------------------------------------
#define P2_WQ 0
#define P2_MH 18432
#define P2_XH 35840
#define P2_SMEM (35840 + 2 * XSTAGE)

__global__ void __launch_bounds__(384, 1) p2(const float* __restrict__ x,
                                             const float* __restrict__ w_qkv) {
    extern __shared__ char sm[];
    __half* WQ = (__half*)(sm + P2_WQ);                 // [128 hd][72 c]
    __half* MH = (__half*)(sm + P2_MH);                 // [64 co][136 hd]
    char* XHb = sm + P2_XH;                             // 2 stages [64 c][136 pos]
    const int t = threadIdx.x, w = t >> 5, lane = t & 31;
    const int b = blockIdx.y, stripe = blockIdx.x;
    const float* xb = x + (size_t)b * 64 * HW;

    for (int i = t; i < 8192; i += 384) {
        int r = i >> 6, c = i & 63;
        WQ[r * 72 + c] = __float2half(w_qkv[r * 64 + c]);
    }
    for (int i = t; i < 8192; i += 384) {
        int co = i >> 7, hd = i & 127;
        MH[co * 136 + hd] = __float2half(g_M[(size_t)b * 8192 + i]);
    }
    __syncthreads();

    if (t >= 256) {
        const int tp = t - 256, pw = tp >> 5, pl = tp & 31, p4 = pl * 4;
        for (int ci = 0; ci < 4; ci++) {
            const int stage = ci & 1;
            if (ci >= 2) BAR_SYNC(3 + stage, 384);
            char* xh = XHb + stage * XSTAGE;
            const int pos0 = (stripe * 4 + ci) * 128;
#pragma unroll
            for (int j = 0; j < 16; j++) {
                int c = pw * 16 + j;
                float4 v = *(const float4*)&xb[(size_t)c * HW + pos0 + p4];
                *(uint2*)(xh + c * 272 + p4 * 2) =
                    make_uint2(pkh(v.x, v.y), pkh(v.z, v.w));
            }
            BAR_ARR(1 + stage, 384);
        }
        return;
    }

    // ---- consumer: warp w owns pos [w*16, w*16+16) of each 128-pos chunk ----
    const int g = lane >> 2, cq = lane & 3;
    const int l7 = lane & 7, l8 = (lane >> 3) & 1, lhi = lane >> 4;
    const uint32_t WQs = cvta_s(WQ), MHs = cvta_s(MH), XHs0 = cvta_s(XHb);
    // A (x^T) trans-load: rows k=c, col base = this warp's pos
    const uint32_t axoff = (uint32_t)((l7 + lhi * 8) * 272 + (w * 16 + l8 * 8) * 2);
    // B row base for WQ ([n=hd][k=c]) and MH ([n=co][k=hd]) non-trans loads
    const uint32_t nrow = (uint32_t)(l7 + lhi * 8);

    float s1[8][2], s2[8][2];
#pragma unroll
    for (int nt = 0; nt < 8; nt++) {
        s1[nt][0] = s1[nt][1] = 0.f;
        s2[nt][0] = s2[nt][1] = 0.f;
    }

    for (int ci = 0; ci < 4; ci++) {
        const int stage = ci & 1;
        BAR_SYNC(1 + stage, 384);
        const uint32_t XHs = XHs0 + stage * XSTAGE;
        const int pos0 = (stripe * 4 + ci) * 128;

        // q^T GEMM: D[pos 16][hd 128]
        float D[16][4];
#pragma unroll
        for (int nt = 0; nt < 16; nt++)
#pragma unroll
            for (int r = 0; r < 4; r++) D[nt][r] = 0.f;
#pragma unroll
        for (int ks = 0; ks < 4; ks++) {
            uint32_t AX[4];
            ldsm4t(AX, XHs + axoff + ks * 16 * 272);
#pragma unroll
            for (int nt2 = 0; nt2 < 8; nt2++) {
                uint32_t BQ[4];
                ldsm4(BQ, WQs + (nt2 * 16 + nrow) * 144 + (ks * 16 + l8 * 8) * 2);
                MMA(D[2 * nt2], AX, BQ);
                MMA(D[2 * nt2 + 1], AX, BQ + 2);
            }
        }
        BAR_ARR(3 + stage, 384);   // X stage free; producers prefetch next

        // softmax over hd within each head (32 cols); rows are pos
        const float scale = 0.17677669529663687f;
#pragma unroll
        for (int nt = 0; nt < 16; nt++)
#pragma unroll
            for (int r = 0; r < 4; r++) D[nt][r] = __expf(D[nt][r]);
#pragma unroll
        for (int h = 0; h < 4; h++) {
            float slo = 0.f, shi = 0.f;
#pragma unroll
            for (int j = 0; j < 4; j++) {
                slo += D[4 * h + j][0] + D[4 * h + j][1];
                shi += D[4 * h + j][2] + D[4 * h + j][3];
            }
            slo += __shfl_xor_sync(~0u, slo, 1);
            slo += __shfl_xor_sync(~0u, slo, 2);
            shi += __shfl_xor_sync(~0u, shi, 1);
            shi += __shfl_xor_sync(~0u, shi, 2);
            float rlo = __fdividef(scale, slo);
            float rhi = __fdividef(scale, shi);
#pragma unroll
            for (int j = 0; j < 4; j++) {
                D[4 * h + j][0] *= rlo; D[4 * h + j][1] *= rlo;
                D[4 * h + j][2] *= rhi; D[4 * h + j][3] *= rhi;
            }
        }

        // out^T GEMM: O[pos 16][co 64]; A straight from D regs
        float O[8][4];
#pragma unroll
        for (int nt = 0; nt < 8; nt++)
#pragma unroll
            for (int r = 0; r < 4; r++) O[nt][r] = 0.f;
#pragma unroll
        for (int ks = 0; ks < 8; ks++) {
            uint32_t AA[4];
            AA[0] = pkh(D[2 * ks][0], D[2 * ks][1]);
            AA[1] = pkh(D[2 * ks][2], D[2 * ks][3]);
            AA[2] = pkh(D[2 * ks + 1][0], D[2 * ks + 1][1]);
            AA[3] = pkh(D[2 * ks + 1][2], D[2 * ks + 1][3]);
#pragma unroll
            for (int nt2 = 0; nt2 < 4; nt2++) {
                uint32_t BM[4];
                ldsm4(BM, MHs + (nt2 * 16 + nrow) * 272 + (ks * 16 + l8 * 8) * 2);
                MMA(O[2 * nt2], AA, BM);
                MMA(O[2 * nt2 + 1], AA, BM + 2);
            }
        }

        // epilogue: scattered-by-channel stores + stats (no bias; BN absorbs)
        const int posr = pos0 + w * 16 + g;
#pragma unroll
        for (int nt = 0; nt < 8; nt++) {
            int co = nt * 8 + 2 * cq;
            float v0 = O[nt][0], v1 = O[nt][1], v2 = O[nt][2], v3 = O[nt][3];
            g_prebn[((size_t)(b * 64 + co)) * HW + posr] = v0;
            g_prebn[((size_t)(b * 64 + co + 1)) * HW + posr] = v1;
            g_prebn[((size_t)(b * 64 + co)) * HW + posr + 8] = v2;
            g_prebn[((size_t)(b * 64 + co + 1)) * HW + posr + 8] = v3;
            s1[nt][0] += v0 + v2; s1[nt][1] += v1 + v3;
            s2[nt][0] += v0 * v0 + v2 * v2; s2[nt][1] += v1 * v1 + v3 * v3;
        }
    }
    // final stats: reduce over pos lanes (g), stage per block
    BAR_SYNC(5, 256);              // all warps done reading WQ
    float* st1 = (float*)sm;       // reuse WQ region
    float* st2 = st1 + 512;
#pragma unroll
    for (int nt = 0; nt < 8; nt++)
#pragma unroll
        for (int c2 = 0; c2 < 2; c2++) {
            s1[nt][c2] += __shfl_xor_sync(~0u, s1[nt][c2], 4);
            s1[nt][c2] += __shfl_xor_sync(~0u, s1[nt][c2], 8);
            s1[nt][c2] += __shfl_xor_sync(~0u, s1[nt][c2], 16);
            s2[nt][c2] += __shfl_xor_sync(~0u, s2[nt][c2], 4);
            s2[nt][c2] += __shfl_xor_sync(~0u, s2[nt][c2], 8);
            s2[nt][c2] += __shfl_xor_sync(~0u, s2[nt][c2], 16);
        }
    if (lane < 4) {
#pragma unroll
        for (int nt = 0; nt < 8; nt++)
#pragma unroll
            for (int c2 = 0; c2 < 2; c2++) {
                int co = nt * 8 + 2 * cq + c2;
                st1[co * 8 + w] = s1[nt][c2];
                st2[co * 8 + w] = s2[nt][c2];
            }
    }
    BAR_SYNC(5, 256);
    if (t < 64) {
        float a = 0.f, c2s = 0.f;
#pragma unroll
        for (int j = 0; j < 8; j++) { a += st1[t * 8 + j]; c2s += st2[t * 8 + j]; }
        int blk = b * 32 + stripe;
        g_statsP[blk * 128 + t] = a;
        g_statsP[blk * 128 + 64 + t] = c2s;
    }
}

// ---------------------------------------------------------------------------
// k4b: finalize BN stats (bias-free prebn: shift = beta - mean_v*sc is exact
// because channel bias cancels in BN). k5: affine.
// ---------------------------------------------------------------------------
__global__ void __launch_bounds__(128) k4b(const float* __restrict__ gamma,
                                           const float* __restrict__ beta) {
    __shared__ float a1[128], a2[128];
    const int c = blockIdx.x, t = threadIdx.x;
    float s1 = 0.f, s2 = 0.f;
    for (int blk = t; blk < 512; blk += 128) {
        s1 += g_statsP[blk * 128 + c];
        s2 += g_statsP[blk * 128 + 64 + c];
    }
    a1[t] = s1; a2[t] = s2;
    __syncthreads();
    for (int o = 64; o > 0; o >>= 1) {
        if (t < o) { a1[t] += a1[t + o]; a2[t] += a2[t + o]; }
        __syncthreads();
    }
    if (t == 0) {
        const float invN = 1.0f / 262144.0f;
        float mean = a1[0] * invN;
        float var = a2[0] * invN - mean * mean;
        float sc = gamma[c] * rsqrtf(var + 1e-5f);
        g_scale[c] = sc;
        g_shift[c] = beta[c] - mean * sc;
    }
}

__global__ void __launch_bounds__(256) k5_affine(float* __restrict__ out) {
    int i4 = blockIdx.x * 256 + threadIdx.x;
    int c = (i4 >> 12) & 63;
    float4 v = ((const float4*)g_prebn)[i4];
    float s = g_scale[c], sh = g_shift[c];
    v.x = fmaf(v.x, s, sh); v.y = fmaf(v.y, s, sh);
    v.z = fmaf(v.z, s, sh); v.w = fmaf(v.w, s, sh);
    ((float4*)out)[i4] = v;
}

extern "C" void kernel_launch(void* const* d_in, const int* in_sizes, int n_in,
                              void* d_out, int out_size) {
    const float* x     = (const float*)d_in[0];
    const float* w_qkv = (const float*)d_in[1];
    const float* w_out = (const float*)d_in[2];
    const float* gamma = (const float*)d_in[4];
    const float* beta  = (const float*)d_in[5];
    float* out = (float*)d_out;

    cudaFuncSetAttribute(p1, cudaFuncAttributeMaxDynamicSharedMemorySize, P1_SMEM);
    cudaFuncSetAttribute(p2, cudaFuncAttributeMaxDynamicSharedMemorySize, P2_SMEM);

    // 2 hidden harness launches + p1 + k2a + k2b -> p2 at ncu's skip-5 slot
    p1<<<dim3(32, 16), 384, P1_SMEM>>>(x, w_qkv);
    k2a<<<dim3(16, 8), 256>>>();
    k2b<<<16, 256>>>(w_qkv, w_out);
    p2<<<dim3(32, 16), 384, P2_SMEM>>>(x, w_qkv);
    k4b<<<64, 128>>>(gamma, beta);
    k5_affine<<<16384, 256>>>(out);
}

// round 16
// speedup vs baseline: 1.7635x; 1.4864x over previous
#include <cuda_runtime.h>
#include <cuda_fp16.h>
#include <cstdint>

#define HW 16384

__device__ float g_Gp[16 * 32 * 8192];        // G partials [b][stripe][hd*64+c]
__device__ float g_G[16 * 8192];              // reduced G [b][hd*64+c]
__device__ float g_M[16 * 8192];              // folded M [b][co*128+hd]
__device__ __half g_prebn[16 * 64 * 16384];   // pre-BN (no bias; BN absorbs), fp16
__device__ float g_statsP[512 * 128];         // per p2-block [s1 x64 | s2 x64]
__device__ float g_scale[64], g_shift[64];
__device__ int g_cnt_b[16];                   // k2a per-batch arrival counters
__device__ int g_cnt_all;                     // p2 global arrival counter

static __device__ __forceinline__ uint32_t pkh(float lo, float hi) {
    uint32_t r;
    asm("cvt.rn.f16x2.f32 %0,%1,%2;" : "=r"(r) : "f"(hi), "f"(lo));
    return r;
}
static __device__ __forceinline__ void MMA(float* d, const uint32_t* a,
                                           const uint32_t* b) {
    asm volatile(
        "mma.sync.aligned.m16n8k16.row.col.f32.f16.f16.f32 "
        "{%0,%1,%2,%3},{%4,%5,%6,%7},{%8,%9},{%0,%1,%2,%3};"
        : "+f"(d[0]), "+f"(d[1]), "+f"(d[2]), "+f"(d[3])
        : "r"(a[0]), "r"(a[1]), "r"(a[2]), "r"(a[3]), "r"(b[0]), "r"(b[1]));
}
static __device__ __forceinline__ uint32_t cvta_s(const void* p) {
    uint32_t a;
    asm("{.reg .u64 t; cvta.to.shared.u64 t,%1; cvt.u32.u64 %0,t;}" : "=r"(a) : "l"(p));
    return a;
}
static __device__ __forceinline__ void ldsm4(uint32_t* r, uint32_t a) {
    asm volatile("ldmatrix.sync.aligned.m8n8.x4.shared.b16 {%0,%1,%2,%3},[%4];"
                 : "=r"(r[0]), "=r"(r[1]), "=r"(r[2]), "=r"(r[3]) : "r"(a));
}
static __device__ __forceinline__ void ldsm4t(uint32_t* r, uint32_t a) {
    asm volatile("ldmatrix.sync.aligned.m8n8.x4.trans.shared.b16 {%0,%1,%2,%3},[%4];"
                 : "=r"(r[0]), "=r"(r[1]), "=r"(r[2]), "=r"(r[3]) : "r"(a));
}
#define BAR_SYNC(id, cnt) asm volatile("bar.sync %0,%1;" :: "r"(id), "r"(cnt) : "memory")
#define BAR_ARR(id, cnt)  asm volatile("bar.arrive %0,%1;" :: "r"(id), "r"(cnt) : "memory")
#define XSTAGE 17408

// ---------------------------------------------------------------------------
// p1: k GEMM + softmax + G GEMM (unchanged; 58us ncu measured)
// ---------------------------------------------------------------------------
#define P1_WH 0
#define P1_XH 18432
#define P1_SMEM (18432 + 2 * XSTAGE)

__global__ void __launch_bounds__(384, 1) p1(const float* __restrict__ x,
                                             const float* __restrict__ w_qkv) {
    extern __shared__ char sm[];
    __half* WH = (__half*)(sm + P1_WH);                 // [128 hd][72 c]
    char* XHb = sm + P1_XH;                             // 2 stages [64 c][136 pos]
    const int t = threadIdx.x, w = t >> 5, lane = t & 31;
    const int b = blockIdx.y, stripe = blockIdx.x;
    const float* xb = x + (size_t)b * 64 * HW;

    for (int i = t; i < 8192; i += 384) {
        int r = i >> 6, c = i & 63;
        WH[r * 72 + c] = __float2half(w_qkv[(128 + r) * 64 + c]);
    }
    __syncthreads();

    if (t >= 256) {
        const int tp = t - 256, pw = tp >> 5, pl = tp & 31, p4 = pl * 4;
        for (int ci = 0; ci < 4; ci++) {
            const int stage = ci & 1;
            if (ci >= 2) BAR_SYNC(3 + stage, 384);
            char* xh = XHb + stage * XSTAGE;
            const int pos0 = (stripe * 4 + ci) * 128;
#pragma unroll
            for (int j = 0; j < 16; j++) {
                int c = pw * 16 + j;
                float4 v = *(const float4*)&xb[(size_t)c * HW + pos0 + p4];
                *(uint2*)(xh + c * 272 + p4 * 2) =
                    make_uint2(pkh(v.x, v.y), pkh(v.z, v.w));
            }
            BAR_ARR(1 + stage, 384);
        }
        return;
    }

    const int h = w >> 1, ng = w & 1, g = lane >> 2, cq = lane & 3;
    const uint32_t WHs = cvta_s(WH);
    const uint32_t XHs0 = cvta_s(XHb);
    const int l15 = lane & 15, lhi = lane >> 4, l7 = lane & 7, l8 = (lane >> 3) & 1;
    const uint32_t aoff = (uint32_t)((h * 32 + l15) * 144 + lhi * 16);

    float G[2][8][4];
#pragma unroll
    for (int a = 0; a < 2; a++)
#pragma unroll
        for (int n = 0; n < 8; n++)
#pragma unroll
            for (int r = 0; r < 4; r++) G[a][n][r] = 0.f;

    for (int ci = 0; ci < 4; ci++) {
        const int stage = ci & 1;
        BAR_SYNC(1 + stage, 384);
        const uint32_t XHs = XHs0 + stage * XSTAGE;

#pragma unroll
        for (int ntp = 0; ntp < 4; ntp++) {
            const int p0 = ng * 64 + ntp * 16;
            float D[2][2][4];
#pragma unroll
            for (int a = 0; a < 2; a++)
#pragma unroll
                for (int n = 0; n < 2; n++)
#pragma unroll
                    for (int r = 0; r < 4; r++) D[a][n][r] = 0.f;

            const uint32_t b1 = (uint32_t)(l15 * 272 + (p0 + lhi * 8) * 2);
#pragma unroll
            for (int ks = 0; ks < 4; ks++) {
                uint32_t BH[4];
                ldsm4t(BH, XHs + b1 + ks * 16 * 272);
#pragma unroll
                for (int mt = 0; mt < 2; mt++) {
                    uint32_t AH[4];
                    ldsm4(AH, WHs + aoff + mt * 2304 + ks * 32);
                    MMA(D[mt][0], AH, BH);
                    MMA(D[mt][1], AH, BH + 2);
                }
            }
#pragma unroll
            for (int nt2 = 0; nt2 < 2; nt2++)
#pragma unroll
                for (int pr = 0; pr < 2; pr++) {
                    float v0 = __expf(D[0][nt2][pr]);
                    float v1 = __expf(D[0][nt2][pr + 2]);
                    float v2 = __expf(D[1][nt2][pr]);
                    float v3 = __expf(D[1][nt2][pr + 2]);
                    float s = v0 + v1 + v2 + v3;
                    s += __shfl_xor_sync(~0u, s, 4);
                    s += __shfl_xor_sync(~0u, s, 8);
                    s += __shfl_xor_sync(~0u, s, 16);
                    float r = __fdividef(1.0f, s);
                    D[0][nt2][pr] = v0 * r; D[0][nt2][pr + 2] = v1 * r;
                    D[1][nt2][pr] = v2 * r; D[1][nt2][pr + 2] = v3 * r;
                }
            uint32_t A2[2][4];
#pragma unroll
            for (int mt = 0; mt < 2; mt++) {
                A2[mt][0] = pkh(D[mt][0][0], D[mt][0][1]);
                A2[mt][1] = pkh(D[mt][0][2], D[mt][0][3]);
                A2[mt][2] = pkh(D[mt][1][0], D[mt][1][1]);
                A2[mt][3] = pkh(D[mt][1][2], D[mt][1][3]);
            }
#pragma unroll
            for (int ct = 0; ct < 4; ct++) {
                uint32_t BH[4];
                uint32_t bo = (uint32_t)((ct * 16 + l7 + lhi * 8) * 272 +
                                         (p0 + l8 * 8) * 2);
                ldsm4(BH, XHs + bo);
#pragma unroll
                for (int mt = 0; mt < 2; mt++) {
                    MMA(G[mt][2 * ct], A2[mt], BH);
                    MMA(G[mt][2 * ct + 1], A2[mt], BH + 2);
                }
            }
        }
        BAR_ARR(3 + stage, 384);
    }
    BAR_SYNC(5, 256);
    float* Gs = (float*)sm;
    if (ng == 1) {
#pragma unroll
        for (int mt = 0; mt < 2; mt++)
#pragma unroll
            for (int nt = 0; nt < 8; nt++)
#pragma unroll
                for (int r = 0; r < 4; r++) {
                    int row = h * 32 + mt * 16 + g + ((r >> 1) ? 8 : 0);
                    int col = nt * 8 + 2 * cq + (r & 1);
                    Gs[row * 64 + col] = G[mt][nt][r];
                }
    }
    BAR_SYNC(5, 256);
    if (ng == 0) {
        float* op = g_Gp + ((size_t)(b * 32 + stripe)) * 8192;
#pragma unroll
        for (int mt = 0; mt < 2; mt++)
#pragma unroll
            for (int nt = 0; nt < 8; nt++)
#pragma unroll
                for (int r = 0; r < 4; r++) {
                    int row = h * 32 + mt * 16 + g + ((r >> 1) ? 8 : 0);
                    int col = nt * 8 + 2 * cq + (r & 1);
                    op[row * 64 + col] = G[mt][nt][r] + Gs[row * 64 + col];
                }
    }
}

// ---------------------------------------------------------------------------
// k2a: parallel stripe reduction g_Gp -> g_G; per-b LAST block (fence+atomic)
// folds ctx + M for that b. Deterministic, counter self-resets.
// ---------------------------------------------------------------------------
__global__ void __launch_bounds__(256) k2a(const float* __restrict__ w_qkv,
                                           const float* __restrict__ w_out) {
    __shared__ float S[8192];
    __shared__ int s_old;
    const int b = blockIdx.x, seg = blockIdx.y, t = threadIdx.x;
    const int i0 = seg * 1024;
    for (int j = t; j < 1024; j += 256) {
        int i = i0 + j;
        const float* p = g_Gp + (size_t)b * 32 * 8192 + i;
        float s = 0.f;
#pragma unroll
        for (int st = 0; st < 32; st++) s += p[(size_t)st * 8192];
        g_G[(size_t)b * 8192 + i] = s;
    }
    __threadfence();            // each writer fences its g_G writes
    __syncthreads();
    if (t == 0) s_old = atomicAdd(&g_cnt_b[b], 1);
    __syncthreads();
    if (s_old != 7) return;     // only last-arriving block folds
    if (t == 0) g_cnt_b[b] = 0; // reset for graph replay
    for (int i = t; i < 8192; i += 256) S[i] = g_G[(size_t)b * 8192 + i];
    __syncthreads();
    float cs[16];
#pragma unroll
    for (int jj = 0; jj < 16; jj++) {
        int i = t + jj * 256;
        int hh = i >> 10, d = (i >> 5) & 31, e = i & 31;
        const float* gr = S + (hh * 32 + d) * 64;
        const float* wv = w_qkv + (256 + hh * 32 + e) * 64;
        float s = 0.f;
#pragma unroll
        for (int c = 0; c < 64; c++) s += gr[c] * wv[c];
        cs[jj] = s;
    }
    __syncthreads();
#pragma unroll
    for (int jj = 0; jj < 16; jj++) S[t + jj * 256] = cs[jj];   // Cs overwrites Gs
    __syncthreads();
    for (int i = t; i < 8192; i += 256) {
        int co = i >> 7, hd = i & 127, hh = hd >> 5, d = hd & 31;
        const float* wo = w_out + co * 128 + hh * 32;
        const float* cc = S + hh * 1024 + d * 32;
        float s = 0.f;
#pragma unroll
        for (int e = 0; e < 32; e++) s += wo[e] * cc[e];
        g_M[(size_t)b * 8192 + i] = s;
    }
}

// ---------------------------------------------------------------------------
// p2: transposed q GEMM + in-reg softmax + out GEMM (A from regs), fp16 prebn
// stores, fused stats. Global LAST block computes BN scale/shift (k4b fused).
// 8 consumer + 4 producer warps. Grid (32,16).
// ---------------------------------------------------------------------------
#define P2_WQ 0
#define P2_MH 18432
#define P2_XH 35840
#define P2_SMEM (35840 + 2 * XSTAGE)

__global__ void __launch_bounds__(384, 1) p2(const float* __restrict__ x,
                                             const float* __restrict__ w_qkv,
                                             const float* __restrict__ gamma,
                                             const float* __restrict__ beta) {
    extern __shared__ char sm[];
    __shared__ int s_last;
    __half* WQ = (__half*)(sm + P2_WQ);                 // [128 hd][72 c]
    __half* MH = (__half*)(sm + P2_MH);                 // [64 co][136 hd]
    char* XHb = sm + P2_XH;                             // 2 stages [64 c][136 pos]
    const int t = threadIdx.x, w = t >> 5, lane = t & 31;
    const int b = blockIdx.y, stripe = blockIdx.x;
    const float* xb = x + (size_t)b * 64 * HW;

    for (int i = t; i < 8192; i += 384) {
        int r = i >> 6, c = i & 63;
        WQ[r * 72 + c] = __float2half(w_qkv[r * 64 + c]);
    }
    for (int i = t; i < 8192; i += 384) {
        int co = i >> 7, hd = i & 127;
        MH[co * 136 + hd] = __float2half(g_M[(size_t)b * 8192 + i]);
    }
    __syncthreads();

    if (t >= 256) {
        const int tp = t - 256, pw = tp >> 5, pl = tp & 31, p4 = pl * 4;
        for (int ci = 0; ci < 4; ci++) {
            const int stage = ci & 1;
            if (ci >= 2) BAR_SYNC(3 + stage, 384);
            char* xh = XHb + stage * XSTAGE;
            const int pos0 = (stripe * 4 + ci) * 128;
#pragma unroll
            for (int j = 0; j < 16; j++) {
                int c = pw * 16 + j;
                float4 v = *(const float4*)&xb[(size_t)c * HW + pos0 + p4];
                *(uint2*)(xh + c * 272 + p4 * 2) =
                    make_uint2(pkh(v.x, v.y), pkh(v.z, v.w));
            }
            BAR_ARR(1 + stage, 384);
        }
        return;
    }

    const int g = lane >> 2, cq = lane & 3;
    const int l7 = lane & 7, l8 = (lane >> 3) & 1, lhi = lane >> 4;
    const uint32_t WQs = cvta_s(WQ), MHs = cvta_s(MH), XHs0 = cvta_s(XHb);
    const uint32_t axoff = (uint32_t)((l7 + lhi * 8) * 272 + (w * 16 + l8 * 8) * 2);
    const uint32_t nrow = (uint32_t)(l7 + lhi * 8);

    float s1[8][2], s2[8][2];
#pragma unroll
    for (int nt = 0; nt < 8; nt++) {
        s1[nt][0] = s1[nt][1] = 0.f;
        s2[nt][0] = s2[nt][1] = 0.f;
    }

    for (int ci = 0; ci < 4; ci++) {
        const int stage = ci & 1;
        BAR_SYNC(1 + stage, 384);
        const uint32_t XHs = XHs0 + stage * XSTAGE;
        const int pos0 = (stripe * 4 + ci) * 128;

        float D[16][4];
#pragma unroll
        for (int nt = 0; nt < 16; nt++)
#pragma unroll
            for (int r = 0; r < 4; r++) D[nt][r] = 0.f;
#pragma unroll
        for (int ks = 0; ks < 4; ks++) {
            uint32_t AX[4];
            ldsm4t(AX, XHs + axoff + ks * 16 * 272);
#pragma unroll
            for (int nt2 = 0; nt2 < 8; nt2++) {
                uint32_t BQ[4];
                ldsm4(BQ, WQs + (nt2 * 16 + nrow) * 144 + (ks * 16 + l8 * 8) * 2);
                MMA(D[2 * nt2], AX, BQ);
                MMA(D[2 * nt2 + 1], AX, BQ + 2);
            }
        }
        BAR_ARR(3 + stage, 384);

        const float scale = 0.17677669529663687f;
#pragma unroll
        for (int nt = 0; nt < 16; nt++)
#pragma unroll
            for (int r = 0; r < 4; r++) D[nt][r] = __expf(D[nt][r]);
#pragma unroll
        for (int h = 0; h < 4; h++) {
            float slo = 0.f, shi = 0.f;
#pragma unroll
            for (int j = 0; j < 4; j++) {
                slo += D[4 * h + j][0] + D[4 * h + j][1];
                shi += D[4 * h + j][2] + D[4 * h + j][3];
            }
            slo += __shfl_xor_sync(~0u, slo, 1);
            slo += __shfl_xor_sync(~0u, slo, 2);
            shi += __shfl_xor_sync(~0u, shi, 1);
            shi += __shfl_xor_sync(~0u, shi, 2);
            float rlo = __fdividef(scale, slo);
            float rhi = __fdividef(scale, shi);
#pragma unroll
            for (int j = 0; j < 4; j++) {
                D[4 * h + j][0] *= rlo; D[4 * h + j][1] *= rlo;
                D[4 * h + j][2] *= rhi; D[4 * h + j][3] *= rhi;
            }
        }

        float O[8][4];
#pragma unroll
        for (int nt = 0; nt < 8; nt++)
#pragma unroll
            for (int r = 0; r < 4; r++) O[nt][r] = 0.f;
#pragma unroll
        for (int ks = 0; ks < 8; ks++) {
            uint32_t AA[4];
            AA[0] = pkh(D[2 * ks][0], D[2 * ks][1]);
            AA[1] = pkh(D[2 * ks][2], D[2 * ks][3]);
            AA[2] = pkh(D[2 * ks + 1][0], D[2 * ks + 1][1]);
            AA[3] = pkh(D[2 * ks + 1][2], D[2 * ks + 1][3]);
#pragma unroll
            for (int nt2 = 0; nt2 < 4; nt2++) {
                uint32_t BM[4];
                ldsm4(BM, MHs + (nt2 * 16 + nrow) * 272 + (ks * 16 + l8 * 8) * 2);
                MMA(O[2 * nt2], AA, BM);
                MMA(O[2 * nt2 + 1], AA, BM + 2);
            }
        }

        const int posr = pos0 + w * 16 + g;
#pragma unroll
        for (int nt = 0; nt < 8; nt++) {
            int co = nt * 8 + 2 * cq;
            float v0 = O[nt][0], v1 = O[nt][1], v2 = O[nt][2], v3 = O[nt][3];
            g_prebn[((size_t)(b * 64 + co)) * HW + posr] = __float2half(v0);
            g_prebn[((size_t)(b * 64 + co + 1)) * HW + posr] = __float2half(v1);
            g_prebn[((size_t)(b * 64 + co)) * HW + posr + 8] = __float2half(v2);
            g_prebn[((size_t)(b * 64 + co + 1)) * HW + posr + 8] = __float2half(v3);
            s1[nt][0] += v0 + v2; s1[nt][1] += v1 + v3;
            s2[nt][0] += v0 * v0 + v2 * v2; s2[nt][1] += v1 * v1 + v3 * v3;
        }
    }
    // stats staging (per block)
    BAR_SYNC(5, 256);
    float* st1 = (float*)sm;       // reuse WQ region
    float* st2 = st1 + 512;
#pragma unroll
    for (int nt = 0; nt < 8; nt++)
#pragma unroll
        for (int c2 = 0; c2 < 2; c2++) {
            s1[nt][c2] += __shfl_xor_sync(~0u, s1[nt][c2], 4);
            s1[nt][c2] += __shfl_xor_sync(~0u, s1[nt][c2], 8);
            s1[nt][c2] += __shfl_xor_sync(~0u, s1[nt][c2], 16);
            s2[nt][c2] += __shfl_xor_sync(~0u, s2[nt][c2], 4);
            s2[nt][c2] += __shfl_xor_sync(~0u, s2[nt][c2], 8);
            s2[nt][c2] += __shfl_xor_sync(~0u, s2[nt][c2], 16);
        }
    if (lane < 4) {
#pragma unroll
        for (int nt = 0; nt < 8; nt++)
#pragma unroll
            for (int c2 = 0; c2 < 2; c2++) {
                int co = nt * 8 + 2 * cq + c2;
                st1[co * 8 + w] = s1[nt][c2];
                st2[co * 8 + w] = s2[nt][c2];
            }
    }
    BAR_SYNC(5, 256);
    if (t < 64) {
        float a = 0.f, c2s = 0.f;
#pragma unroll
        for (int j = 0; j < 8; j++) { a += st1[t * 8 + j]; c2s += st2[t * 8 + j]; }
        int blk = b * 32 + stripe;
        g_statsP[blk * 128 + t] = a;
        g_statsP[blk * 128 + 64 + t] = c2s;
    }
    // fused BN-stat finalize: global last block computes scale/shift
    __threadfence();               // each writer fences its statsP writes
    BAR_SYNC(5, 256);
    if (t == 0) {
        int oldv = atomicAdd(&g_cnt_all, 1);
        s_last = (oldv == 511);
        if (oldv == 511) g_cnt_all = 0;    // reset for graph replay
    }
    BAR_SYNC(5, 256);
    if (!s_last) return;
    {
        float* a1 = (float*)sm;
        float* a2 = a1 + 256;
        const int c = t & 63, part = t >> 6;
        float s1t = 0.f, s2t = 0.f;
        for (int blk = part; blk < 512; blk += 4) {
            s1t += g_statsP[blk * 128 + c];
            s2t += g_statsP[blk * 128 + 64 + c];
        }
        BAR_SYNC(5, 256);          // smem reuse safe (prior reads done)
        a1[t] = s1t; a2[t] = s2t;
        BAR_SYNC(5, 256);
        if (t < 64) {
            float S1 = a1[t] + a1[t + 64] + a1[t + 128] + a1[t + 192];
            float S2 = a2[t] + a2[t + 64] + a2[t + 128] + a2[t + 192];
            const float invN = 1.0f / 262144.0f;
            float mean = S1 * invN;
            float var = S2 * invN - mean * mean;
            float sc = gamma[t] * rsqrtf(var + 1e-5f);
            g_scale[t] = sc;
            g_shift[t] = beta[t] - mean * sc;
        }
    }
}

// ---------------------------------------------------------------------------
// k5: affine from fp16 prebn (96MB traffic). 8 halves per thread.
// ---------------------------------------------------------------------------
__global__ void __launch_bounds__(256) k5_affine(float* __restrict__ out) {
    int i8 = blockIdx.x * 256 + threadIdx.x;   // 2,097,152 total
    int c = (i8 >> 11) & 63;                   // 2048 8-elem chunks per (b,c) row
    uint4 v = ((const uint4*)g_prebn)[i8];
    const __half2* hp = (const __half2*)&v;
    float s = g_scale[c], sh = g_shift[c];
    float2 f0 = __half22float2(hp[0]);
    float2 f1 = __half22float2(hp[1]);
    float2 f2 = __half22float2(hp[2]);
    float2 f3 = __half22float2(hp[3]);
    float4 o0, o1;
    o0.x = fmaf(f0.x, s, sh); o0.y = fmaf(f0.y, s, sh);
    o0.z = fmaf(f1.x, s, sh); o0.w = fmaf(f1.y, s, sh);
    o1.x = fmaf(f2.x, s, sh); o1.y = fmaf(f2.y, s, sh);
    o1.z = fmaf(f3.x, s, sh); o1.w = fmaf(f3.y, s, sh);
    ((float4*)out)[i8 * 2] = o0;
    ((float4*)out)[i8 * 2 + 1] = o1;
}

extern "C" void kernel_launch(void* const* d_in, const int* in_sizes, int n_in,
                              void* d_out, int out_size) {
    const float* x     = (const float*)d_in[0];
    const float* w_qkv = (const float*)d_in[1];
    const float* w_out = (const float*)d_in[2];
    const float* gamma = (const float*)d_in[4];
    const float* beta  = (const float*)d_in[5];
    float* out = (float*)d_out;

    cudaFuncSetAttribute(p1, cudaFuncAttributeMaxDynamicSharedMemorySize, P1_SMEM);
    cudaFuncSetAttribute(p2, cudaFuncAttributeMaxDynamicSharedMemorySize, P2_SMEM);

    p1<<<dim3(32, 16), 384, P1_SMEM>>>(x, w_qkv);
    k2a<<<dim3(16, 8), 256>>>(w_qkv, w_out);
    p2<<<dim3(32, 16), 384, P2_SMEM>>>(x, w_qkv, gamma, beta);
    k5_affine<<<8192, 256>>>(out);
}